// round 5
// baseline (speedup 1.0000x reference)
#include <cuda_runtime.h>
#include <math.h>

#define NS 512
#define DD 400
#define HH 400

typedef unsigned long long u64;

// ---- scratch (no allocations allowed) ----
__device__ float  g_hxT[HH * NS];   // transposed: [h][sample]
__device__ float  g_hyT[HH * NS];   // transposed, b1 folded in
__device__ float  g_expsum[NS];     // per-row sum of exp(T1) = 1 + e^v
__device__ double g_tsum;           // sum of all T1
__device__ double g_dsum;           // sum of diag T1 (== T0 sum)
__device__ int    g_cnt = 0;

// ---- packed f32x2 helpers (sm_10x) ----
#define PACK2(d, lo, hi) \
    asm("mov.b64 %0, {%1,%2};" : "=l"(d) : "f"(lo), "f"(hi))
#define FMA2(acc, a, b) \
    asm("fma.rn.f32x2 %0, %1, %2, %0;" : "+l"(acc) : "l"(a), "l"(b))
// acc2 += relu(y2 + x2) * w2   (componentwise)
#define RELU_FMA2(acc, y2, x2, w2)                      \
    asm("{\n\t"                                         \
        ".reg .b64 t;\n\t"                              \
        ".reg .f32 lo, hi;\n\t"                         \
        "add.rn.f32x2 t, %1, %2;\n\t"                   \
        "mov.b64 {lo, hi}, t;\n\t"                      \
        "max.f32 lo, lo, 0f00000000;\n\t"               \
        "max.f32 hi, hi, 0f00000000;\n\t"               \
        "mov.b64 t, {lo, hi};\n\t"                      \
        "fma.rn.f32x2 %0, t, %3, %0;\n\t"               \
        "}" : "+l"(acc) : "l"(y2), "l"(x2), "l"(w2))

// ======================================================================
// Kernel 1: dual GEMM, transposed output.
//   z=0: g_hxT[h][m] = sum_k x[m,k] W1[h,k]
//   z=1: g_hyT[h][m] = sum_k y[m,k] W1[h,400+k] + b1[h]
// Tile 32h x 128m, BK=16, 256 threads, thread tile 2h x 8m.
// Packed-dup H in smem (no inner PACK), double-buffered, 1 sync/tile.
// Grid (4 m, 13 h, 2 z) = 104 blocks.
// ======================================================================
__global__ void __launch_bounds__(256, 1)
gemm_h_kernel(const float* __restrict__ x,
              const float* __restrict__ y,
              const float* __restrict__ W1,
              const float* __restrict__ b1) {
    const int z = blockIdx.z;

    if (z == 0 && blockIdx.x == 0 && blockIdx.y == 0) {
        g_expsum[threadIdx.x] = 0.f;
        g_expsum[threadIdx.x + 256] = 0.f;
        if (threadIdx.x == 0) { g_tsum = 0.0; g_dsum = 0.0; g_cnt = 0; }
    }

    const float* A   = z ? y : x;
    const int   woff = z ? DD : 0;
    float*      outT = z ? g_hyT : g_hxT;

    const int m0 = blockIdx.x * 128;
    const int h0 = blockIdx.y * 32;

    __shared__ __align__(16) float As[2][16][128];  // [buf][k][m]
    __shared__ __align__(16) u64   Hd[2][16][32];   // [buf][k][h] packed (w,w)

    const int tid = threadIdx.x;       // 256
    const int tx  = tid & 15;          // m group: 8 m each
    const int ty  = tid >> 4;          // h group: 2 h each (0..15)

    const int as_m = tid & 127;
    const int as_k = (tid >> 7) * 8;
    const int hh   = tid & 31;
    const int hk   = (tid >> 5) * 2;
    const bool h_ok = (h0 + hh) < HH;

    float4 a_r0, a_r1;
    float2 h_r;

    // load tile 0
    a_r0 = *reinterpret_cast<const float4*>(&A[(m0 + as_m) * DD + as_k]);
    a_r1 = *reinterpret_cast<const float4*>(&A[(m0 + as_m) * DD + as_k + 4]);
    h_r  = make_float2(0.f, 0.f);
    if (h_ok)
        h_r = *reinterpret_cast<const float2*>(&W1[(h0 + hh) * (2 * DD) + woff + hk]);

    // store tile 0 into buffer 0
    {
        As[0][as_k + 0][as_m] = a_r0.x; As[0][as_k + 1][as_m] = a_r0.y;
        As[0][as_k + 2][as_m] = a_r0.z; As[0][as_k + 3][as_m] = a_r0.w;
        As[0][as_k + 4][as_m] = a_r1.x; As[0][as_k + 5][as_m] = a_r1.y;
        As[0][as_k + 6][as_m] = a_r1.z; As[0][as_k + 7][as_m] = a_r1.w;
        u64 p0, p1;
        PACK2(p0, h_r.x, h_r.x); PACK2(p1, h_r.y, h_r.y);
        Hd[0][hk][hh] = p0; Hd[0][hk + 1][hh] = p1;
    }
    __syncthreads();

    u64 acc[2][4] = {};   // [ih][m-pair]

    const int NT = DD / 16;   // 25
    for (int t = 0; t < NT; t++) {
        const int p = t & 1;

        // prefetch tile t+1 into regs
        if (t + 1 < NT) {
            int k0 = (t + 1) * 16;
            a_r0 = *reinterpret_cast<const float4*>(&A[(m0 + as_m) * DD + k0 + as_k]);
            a_r1 = *reinterpret_cast<const float4*>(&A[(m0 + as_m) * DD + k0 + as_k + 4]);
            if (h_ok)
                h_r = *reinterpret_cast<const float2*>(&W1[(h0 + hh) * (2 * DD) + woff + k0 + hk]);
        }

        // compute on buffer p
        #pragma unroll
        for (int kk = 0; kk < 16; kk++) {
            ulonglong2 hp = *reinterpret_cast<const ulonglong2*>(&Hd[p][kk][ty * 2]);
            ulonglong2 ma = *reinterpret_cast<const ulonglong2*>(&As[p][kk][tx * 8 + 0]);
            ulonglong2 mb = *reinterpret_cast<const ulonglong2*>(&As[p][kk][tx * 8 + 4]);
            FMA2(acc[0][0], hp.x, ma.x); FMA2(acc[0][1], hp.x, ma.y);
            FMA2(acc[0][2], hp.x, mb.x); FMA2(acc[0][3], hp.x, mb.y);
            FMA2(acc[1][0], hp.y, ma.x); FMA2(acc[1][1], hp.y, ma.y);
            FMA2(acc[1][2], hp.y, mb.x); FMA2(acc[1][3], hp.y, mb.y);
        }

        // stage tile t+1 into the other buffer; single sync per tile
        if (t + 1 < NT) {
            const int q = 1 - p;
            As[q][as_k + 0][as_m] = a_r0.x; As[q][as_k + 1][as_m] = a_r0.y;
            As[q][as_k + 2][as_m] = a_r0.z; As[q][as_k + 3][as_m] = a_r0.w;
            As[q][as_k + 4][as_m] = a_r1.x; As[q][as_k + 5][as_m] = a_r1.y;
            As[q][as_k + 6][as_m] = a_r1.z; As[q][as_k + 7][as_m] = a_r1.w;
            u64 p0, p1;
            PACK2(p0, h_r.x, h_r.x); PACK2(p1, h_r.y, h_r.y);
            Hd[q][hk][hh] = p0; Hd[q][hk + 1][hh] = p1;
            __syncthreads();
        }
    }

    #pragma unroll
    for (int ih = 0; ih < 2; ih++) {
        int h = h0 + ty * 2 + ih;
        if (h < HH) {
            float2 p0 = *reinterpret_cast<float2*>(&acc[ih][0]);
            float2 p1 = *reinterpret_cast<float2*>(&acc[ih][1]);
            float2 p2 = *reinterpret_cast<float2*>(&acc[ih][2]);
            float2 p3 = *reinterpret_cast<float2*>(&acc[ih][3]);
            if (z) {
                float b = b1[h];
                p0.x += b; p0.y += b; p1.x += b; p1.y += b;
                p2.x += b; p2.y += b; p3.x += b; p3.y += b;
            }
            float* o = &outT[h * NS + m0 + tx * 8];
            *reinterpret_cast<float4*>(o + 0) = make_float4(p0.x, p0.y, p1.x, p1.y);
            *reinterpret_cast<float4*>(o + 4) = make_float4(p2.x, p2.y, p3.x, p3.y);
        }
    }
}

// ======================================================================
// Kernel 2: pair relu-dot + fused epilogue + last-block finalize.
//   v[i,j] = sum_h relu(g_hyT[h][i] + g_hxT[h][j]) * W2[h] + b2
// Tile 32i x 64j, 256 threads, thread tile 2i x 4j. Grid (8,16)=128.
// Packed-dup Y & W in smem, double-buffered, 1 sync/tile.
// ======================================================================
__global__ void __launch_bounds__(256, 1)
pair_kernel(const float* __restrict__ W2,
            const float* __restrict__ b2p,
            float* __restrict__ out) {
    const int j0  = blockIdx.x * 64;
    const int i0  = blockIdx.y * 32;
    const int tid = threadIdx.x;    // 256
    const int tx  = tid & 15;       // j group: 4 j each
    const int ty  = tid >> 4;       // i group: 2 i each (0..15)

    __shared__ __align__(16) u64   Yd[2][16][32];   // packed (y,y) per i
    __shared__ __align__(16) float Xs[2][16][64];
    __shared__ __align__(16) u64   Wp[2][16];

    // staging indices: Y: 16 ty-slots x 16 k;  X: 16 j-quads x 16 k
    const int sy_i = tid & 15;       // i-pair index (covers 32 i as float2)
    const int sy_k = tid >> 4;
    const int sx_j = tid & 15;       // j-quad
    const int sx_k = tid >> 4;

    float2 y_r;
    float4 x_r;
    float  w_r = 0.f;

    // load tile 0
    y_r = *reinterpret_cast<const float2*>(&g_hyT[sy_k * NS + i0 + sy_i * 2]);
    x_r = *reinterpret_cast<const float4*>(&g_hxT[sx_k * NS + j0 + sx_j * 4]);
    if (tid < 16) w_r = W2[tid];

    // store tile 0 into buffer 0
    {
        u64 p0, p1;
        PACK2(p0, y_r.x, y_r.x); PACK2(p1, y_r.y, y_r.y);
        Yd[0][sy_k][sy_i * 2] = p0; Yd[0][sy_k][sy_i * 2 + 1] = p1;
        *reinterpret_cast<float4*>(&Xs[0][sx_k][sx_j * 4]) = x_r;
        if (tid < 16) {
            u64 w2; PACK2(w2, w_r, w_r);
            Wp[0][tid] = w2;
        }
    }
    __syncthreads();

    u64 acc[2][2] = {};   // [ii][j-pair]

    const int NT = HH / 16;   // 25
    for (int t = 0; t < NT; t++) {
        const int p = t & 1;

        if (t + 1 < NT) {
            int k0 = (t + 1) * 16;
            y_r = *reinterpret_cast<const float2*>(&g_hyT[(k0 + sy_k) * NS + i0 + sy_i * 2]);
            x_r = *reinterpret_cast<const float4*>(&g_hxT[(k0 + sx_k) * NS + j0 + sx_j * 4]);
            if (tid < 16) w_r = W2[k0 + tid];
        }

        #pragma unroll
        for (int kk = 0; kk < 16; kk++) {
            ulonglong2 yp = *reinterpret_cast<const ulonglong2*>(&Yd[p][kk][ty * 2]);
            ulonglong2 xj = *reinterpret_cast<const ulonglong2*>(&Xs[p][kk][tx * 4]);
            u64 w2 = Wp[p][kk];
            RELU_FMA2(acc[0][0], yp.x, xj.x, w2);
            RELU_FMA2(acc[0][1], yp.x, xj.y, w2);
            RELU_FMA2(acc[1][0], yp.y, xj.x, w2);
            RELU_FMA2(acc[1][1], yp.y, xj.y, w2);
        }

        if (t + 1 < NT) {
            const int q = 1 - p;
            u64 p0, p1;
            PACK2(p0, y_r.x, y_r.x); PACK2(p1, y_r.y, y_r.y);
            Yd[q][sy_k][sy_i * 2] = p0; Yd[q][sy_k][sy_i * 2 + 1] = p1;
            *reinterpret_cast<float4*>(&Xs[q][sx_k][sx_j * 4]) = x_r;
            if (tid < 16) {
                u64 w2; PACK2(w2, w_r, w_r);
                Wp[q][tid] = w2;
            }
            __syncthreads();
        }
    }

    // ---- fused epilogue (accurate math) ----
    const float b2 = b2p[0];
    float tSum = 0.f, dSum = 0.f;

    #pragma unroll
    for (int ii = 0; ii < 2; ii++) {
        const int i = i0 + ty * 2 + ii;
        float2 p01 = *reinterpret_cast<float2*>(&acc[ii][0]);
        float2 p23 = *reinterpret_cast<float2*>(&acc[ii][1]);
        float vq[4] = {p01.x, p01.y, p23.x, p23.y};
        float eRow = 0.f;
        #pragma unroll
        for (int q = 0; q < 4; q++) {
            float v = vq[q] + b2;
            float tt = fmaxf(v, 0.f) + log1pf(expf(-fabsf(v)));
            eRow += 1.f + expf(v);            // exp(softplus(v)) == 1 + e^v
            tSum += tt;
            if (j0 + tx * 4 + q == i) dSum += tt;
        }
        #pragma unroll
        for (int o = 8; o; o >>= 1)
            eRow += __shfl_down_sync(0xffffffffu, eRow, o, 16);
        if (tx == 0) atomicAdd(&g_expsum[i], eRow);
    }

    // block totals
    const int wid = tid >> 5, lane = tid & 31;
    #pragma unroll
    for (int o = 16; o; o >>= 1) {
        tSum += __shfl_down_sync(0xffffffffu, tSum, o);
        dSum += __shfl_down_sync(0xffffffffu, dSum, o);
    }
    __shared__ float wsum[8], wdia[8];
    if (lane == 0) { wsum[wid] = tSum; wdia[wid] = dSum; }
    __syncthreads();
    if (tid == 0) {
        float ts = 0.f, ds = 0.f;
        #pragma unroll
        for (int w = 0; w < 8; w++) { ts += wsum[w]; ds += wdia[w]; }
        atomicAdd(&g_tsum, (double)ts);
        atomicAdd(&g_dsum, (double)ds);
    }

    // ---- last block finalizes (double precision combine) ----
    __threadfence();
    __shared__ int ticket;
    if (tid == 0) ticket = atomicAdd(&g_cnt, 1);
    __syncthreads();
    if (ticket == 8 * 16 - 1) {
        double ls = log((double)g_expsum[tid]) + log((double)g_expsum[tid + 256]);
        #pragma unroll
        for (int o = 16; o; o >>= 1)
            ls += __shfl_down_sync(0xffffffffu, ls, o);
        __shared__ double lw[8];
        if (lane == 0) lw[wid] = ls;
        __syncthreads();
        if (tid == 0) {
            double lsum = 0.0;
            #pragma unroll
            for (int w = 0; w < 8; w++) lsum += lw[w];
            const double n = (double)NS;
            double t0_mean = g_dsum / n;
            out[0] = (float)(t0_mean - (lsum / n - log(n)));   // lower bound
            out[1] = (float)(t0_mean - g_tsum / (n * n));      // upper bound
            g_cnt = 0;
        }
    }
}

// ======================================================================
extern "C" void kernel_launch(void* const* d_in, const int* in_sizes, int n_in,
                              void* d_out, int out_size) {
    const float* x  = (const float*)d_in[0];
    const float* y  = (const float*)d_in[1];
    const float* W1 = (const float*)d_in[2];
    const float* b1 = (const float*)d_in[3];
    const float* W2 = (const float*)d_in[4];
    const float* b2 = (const float*)d_in[5];
    float* out = (float*)d_out;

    dim3 ggrid(NS / 128, (HH + 31) / 32, 2);   // (4, 13, 2) = 104 blocks
    gemm_h_kernel<<<ggrid, 256>>>(x, y, W1, b1);

    dim3 pgrid(NS / 64, NS / 32);              // (8, 16) = 128 blocks
    pair_kernel<<<pgrid, 256>>>(W2, b2, out);
}

// round 6
// speedup vs baseline: 1.9815x; 1.9815x over previous
#include <cuda_runtime.h>
#include <math.h>

#define NS 512
#define DD 400
#define HH 400

typedef unsigned long long u64;

// ---- scratch (no allocations allowed) ----
__device__ float  g_hxT[HH * NS];   // transposed: [h][sample]
__device__ float  g_hyT[HH * NS];   // transposed, b1 folded in
__device__ float  g_expsum[NS];     // per-row sum of exp(T1) = 1 + e^v
__device__ double g_tsum;           // sum of all T1
__device__ double g_dsum;           // sum of diag T1 (== T0 sum)
__device__ int    g_cnt = 0;

// ---- packed f32x2 helpers (sm_10x) ----
#define PACK2(d, lo, hi) \
    asm("mov.b64 %0, {%1,%2};" : "=l"(d) : "f"(lo), "f"(hi))
#define FMA2(acc, a, b) \
    asm("fma.rn.f32x2 %0, %1, %2, %0;" : "+l"(acc) : "l"(a), "l"(b))
// acc2 += relu(y2 + x2) * w2   (componentwise)
#define RELU_FMA2(acc, y2, x2, w2)                      \
    asm("{\n\t"                                         \
        ".reg .b64 t;\n\t"                              \
        ".reg .f32 lo, hi;\n\t"                         \
        "add.rn.f32x2 t, %1, %2;\n\t"                   \
        "mov.b64 {lo, hi}, t;\n\t"                      \
        "max.f32 lo, lo, 0f00000000;\n\t"               \
        "max.f32 hi, hi, 0f00000000;\n\t"               \
        "mov.b64 t, {lo, hi};\n\t"                      \
        "fma.rn.f32x2 %0, t, %3, %0;\n\t"               \
        "}" : "+l"(acc) : "l"(y2), "l"(x2), "l"(w2))

// ======================================================================
// Kernel 1: dual GEMM, transposed output.
//   z=0: g_hxT[h][m] = sum_k x[m,k] W1[h,k]
//   z=1: g_hyT[h][m] = sum_k y[m,k] W1[h,400+k] + b1[h]
// Tile 32h x 32m, BK=16, 128 threads, thread tile 2h x 4m.
// Grid (16 m, 13 h, 2 z) = 416 blocks -> ~11 warps/SM.
// ======================================================================
__global__ void __launch_bounds__(128)
gemm_h_kernel(const float* __restrict__ x,
              const float* __restrict__ y,
              const float* __restrict__ W1,
              const float* __restrict__ b1) {
    const int z = blockIdx.z;

    if (z == 0 && blockIdx.x == 0 && blockIdx.y == 0) {
        #pragma unroll
        for (int r = 0; r < 4; r++) g_expsum[threadIdx.x + r * 128] = 0.f;
        if (threadIdx.x == 0) { g_tsum = 0.0; g_dsum = 0.0; g_cnt = 0; }
    }

    const float* A   = z ? y : x;
    const int   woff = z ? DD : 0;
    float*      outT = z ? g_hyT : g_hxT;

    const int m0 = blockIdx.x * 32;
    const int h0 = blockIdx.y * 32;

    __shared__ __align__(16) float As[16][32];   // [k][m]
    __shared__ __align__(16) u64   Hd[16][32];   // [k][h] packed (w,w)

    const int tid = threadIdx.x;       // 128
    const int tx  = tid & 7;           // m quad: 4 m each (32 m)
    const int ty  = tid >> 3;          // h pair: 2 h each (0..15)

    const int am = tid & 31;
    const int ak = (tid >> 5) * 4;
    const int hh = tid & 31;
    const int hk = (tid >> 5) * 4;
    const bool h_ok = (h0 + hh) < HH;

    float4 a_r, h_r;

    // load tile 0
    a_r = *reinterpret_cast<const float4*>(&A[(m0 + am) * DD + ak]);
    h_r = make_float4(0.f, 0.f, 0.f, 0.f);
    if (h_ok)
        h_r = *reinterpret_cast<const float4*>(&W1[(h0 + hh) * (2 * DD) + woff + hk]);

    u64 acc[2][2] = {};   // [ih][m-pair]

    const int NT = DD / 16;   // 25
    for (int t = 0; t < NT; t++) {
        // store staged tile
        As[ak + 0][am] = a_r.x; As[ak + 1][am] = a_r.y;
        As[ak + 2][am] = a_r.z; As[ak + 3][am] = a_r.w;
        u64 d0, d1, d2, d3;
        PACK2(d0, h_r.x, h_r.x); PACK2(d1, h_r.y, h_r.y);
        PACK2(d2, h_r.z, h_r.z); PACK2(d3, h_r.w, h_r.w);
        Hd[hk + 0][hh] = d0; Hd[hk + 1][hh] = d1;
        Hd[hk + 2][hh] = d2; Hd[hk + 3][hh] = d3;
        __syncthreads();

        // prefetch next tile
        if (t + 1 < NT) {
            int k0 = (t + 1) * 16;
            a_r = *reinterpret_cast<const float4*>(&A[(m0 + am) * DD + k0 + ak]);
            if (h_ok)
                h_r = *reinterpret_cast<const float4*>(&W1[(h0 + hh) * (2 * DD) + woff + k0 + hk]);
        }

        #pragma unroll
        for (int kk = 0; kk < 16; kk++) {
            ulonglong2 hp = *reinterpret_cast<const ulonglong2*>(&Hd[kk][ty * 2]);
            ulonglong2 ma = *reinterpret_cast<const ulonglong2*>(&As[kk][tx * 4]);
            FMA2(acc[0][0], hp.x, ma.x); FMA2(acc[0][1], hp.x, ma.y);
            FMA2(acc[1][0], hp.y, ma.x); FMA2(acc[1][1], hp.y, ma.y);
        }
        __syncthreads();
    }

    #pragma unroll
    for (int ih = 0; ih < 2; ih++) {
        int h = h0 + ty * 2 + ih;
        if (h < HH) {
            float2 p0 = *reinterpret_cast<float2*>(&acc[ih][0]);
            float2 p1 = *reinterpret_cast<float2*>(&acc[ih][1]);
            if (z) {
                float b = b1[h];
                p0.x += b; p0.y += b; p1.x += b; p1.y += b;
            }
            *reinterpret_cast<float4*>(&outT[h * NS + m0 + tx * 4]) =
                make_float4(p0.x, p0.y, p1.x, p1.y);
        }
    }
}

// ======================================================================
// Kernel 2: pair relu-dot + fused epilogue + last-block finalize.
//   v[i,j] = sum_h relu(g_hyT[h][i] + g_hxT[h][j]) * W2[h] + b2
// Tile 32i x 32j, 256 threads, thread tile 2i x 2j (4 outputs).
// k-pair interleaved smem: one LDS.128 feeds TWO k-steps.
// Grid (16, 16) = 256 blocks -> 2048 warps (~14 warps/SM).
// ======================================================================
__global__ void __launch_bounds__(256)
pair_kernel(const float* __restrict__ W2,
            const float* __restrict__ b2p,
            float* __restrict__ out) {
    const int j0  = blockIdx.x * 32;
    const int i0  = blockIdx.y * 32;
    const int tid = threadIdx.x;    // 256
    const int tx  = tid & 15;       // j pair: 2 j each
    const int ty  = tid >> 4;       // i pair: 2 i each (0..15)

    // k-pair interleaved layouts (kp = k>>1, last index = k&1)
    __shared__ __align__(16) u64 Yd[8][32][2];  // [kp][i][k&1] dup'd (y,y)
    __shared__ __align__(16) u64 Xs[8][16][2];  // [kp][j-pair][k&1] packed (xj0,xj1)
    __shared__ __align__(16) u64 Wp[8][2];      // [kp][k&1] dup'd (w,w)

    // staging: 256 threads, y: one float2 each (16k x 16 i-pairs),
    //          x: one float2 each (16k x 16 j-pairs), w: 16 threads
    const int s_p = tid & 15;       // i-pair / j-pair index
    const int s_k = tid >> 4;       // k within tile (0..15)

    float2 y_r, x_r;
    float  w_r = 0.f;

    // load tile 0
    y_r = *reinterpret_cast<const float2*>(&g_hyT[s_k * NS + i0 + s_p * 2]);
    x_r = *reinterpret_cast<const float2*>(&g_hxT[s_k * NS + j0 + s_p * 2]);
    if (tid < 16) w_r = W2[tid];

    u64 acc[2] = {};   // [ii], each packs 2 j

    const int NT = HH / 16;   // 25
    for (int t = 0; t < NT; t++) {
        // store staged tile (k-pair interleaved)
        {
            u64 yd0, yd1, xp;
            PACK2(yd0, y_r.x, y_r.x);
            PACK2(yd1, y_r.y, y_r.y);
            PACK2(xp, x_r.x, x_r.y);
            Yd[s_k >> 1][s_p * 2 + 0][s_k & 1] = yd0;
            Yd[s_k >> 1][s_p * 2 + 1][s_k & 1] = yd1;
            Xs[s_k >> 1][s_p][s_k & 1] = xp;
            if (tid < 16) {
                u64 wd; PACK2(wd, w_r, w_r);
                Wp[tid >> 1][tid & 1] = wd;
            }
        }
        __syncthreads();

        // prefetch next tile
        if (t + 1 < NT) {
            int k0 = (t + 1) * 16;
            y_r = *reinterpret_cast<const float2*>(&g_hyT[(k0 + s_k) * NS + i0 + s_p * 2]);
            x_r = *reinterpret_cast<const float2*>(&g_hxT[(k0 + s_k) * NS + j0 + s_p * 2]);
            if (tid < 16) w_r = W2[k0 + tid];
        }

        // compute: 8 kp steps, each covering 2 k
        #pragma unroll
        for (int kp = 0; kp < 8; kp++) {
            ulonglong2 xk = *reinterpret_cast<const ulonglong2*>(&Xs[kp][tx][0]);
            ulonglong2 yi0 = *reinterpret_cast<const ulonglong2*>(&Yd[kp][ty * 2 + 0][0]);
            ulonglong2 yi1 = *reinterpret_cast<const ulonglong2*>(&Yd[kp][ty * 2 + 1][0]);
            ulonglong2 wv = *reinterpret_cast<const ulonglong2*>(&Wp[kp][0]);
            RELU_FMA2(acc[0], yi0.x, xk.x, wv.x);   // k even
            RELU_FMA2(acc[0], yi0.y, xk.y, wv.y);   // k odd
            RELU_FMA2(acc[1], yi1.x, xk.x, wv.x);
            RELU_FMA2(acc[1], yi1.y, xk.y, wv.y);
        }
        __syncthreads();
    }

    // ---- fused epilogue (accurate math) ----
    const float b2 = b2p[0];
    float tSum = 0.f, dSum = 0.f;

    #pragma unroll
    for (int ii = 0; ii < 2; ii++) {
        const int i = i0 + ty * 2 + ii;
        float2 pv = *reinterpret_cast<float2*>(&acc[ii]);
        float vq[2] = {pv.x, pv.y};
        float eRow = 0.f;
        #pragma unroll
        for (int q = 0; q < 2; q++) {
            float v = vq[q] + b2;
            float tt = fmaxf(v, 0.f) + log1pf(expf(-fabsf(v)));
            eRow += 1.f + expf(v);            // exp(softplus(v)) == 1 + e^v
            tSum += tt;
            if (j0 + tx * 2 + q == i) dSum += tt;
        }
        #pragma unroll
        for (int o = 8; o; o >>= 1)
            eRow += __shfl_down_sync(0xffffffffu, eRow, o, 16);
        if (tx == 0) atomicAdd(&g_expsum[i], eRow);
    }

    // block totals
    const int wid = tid >> 5, lane = tid & 31;
    #pragma unroll
    for (int o = 16; o; o >>= 1) {
        tSum += __shfl_down_sync(0xffffffffu, tSum, o);
        dSum += __shfl_down_sync(0xffffffffu, dSum, o);
    }
    __shared__ float wsum[8], wdia[8];
    if (lane == 0) { wsum[wid] = tSum; wdia[wid] = dSum; }
    __syncthreads();
    if (tid == 0) {
        float ts = 0.f, ds = 0.f;
        #pragma unroll
        for (int w = 0; w < 8; w++) { ts += wsum[w]; ds += wdia[w]; }
        atomicAdd(&g_tsum, (double)ts);
        atomicAdd(&g_dsum, (double)ds);
    }

    // ---- last block finalizes (double precision combine) ----
    __threadfence();
    __shared__ int ticket;
    if (tid == 0) ticket = atomicAdd(&g_cnt, 1);
    __syncthreads();
    if (ticket == 16 * 16 - 1) {
        double ls = log((double)g_expsum[tid]) + log((double)g_expsum[tid + 256]);
        #pragma unroll
        for (int o = 16; o; o >>= 1)
            ls += __shfl_down_sync(0xffffffffu, ls, o);
        __shared__ double lw[8];
        if (lane == 0) lw[wid] = ls;
        __syncthreads();
        if (tid == 0) {
            double lsum = 0.0;
            #pragma unroll
            for (int w = 0; w < 8; w++) lsum += lw[w];
            const double n = (double)NS;
            double t0_mean = g_dsum / n;
            out[0] = (float)(t0_mean - (lsum / n - log(n)));   // lower bound
            out[1] = (float)(t0_mean - g_tsum / (n * n));      // upper bound
            g_cnt = 0;
        }
    }
}

// ======================================================================
extern "C" void kernel_launch(void* const* d_in, const int* in_sizes, int n_in,
                              void* d_out, int out_size) {
    const float* x  = (const float*)d_in[0];
    const float* y  = (const float*)d_in[1];
    const float* W1 = (const float*)d_in[2];
    const float* b1 = (const float*)d_in[3];
    const float* W2 = (const float*)d_in[4];
    const float* b2 = (const float*)d_in[5];
    float* out = (float*)d_out;

    dim3 ggrid(NS / 32, (HH + 31) / 32, 2);   // (16, 13, 2) = 416 blocks
    gemm_h_kernel<<<ggrid, 128>>>(x, y, W1, b1);

    dim3 pgrid(NS / 32, NS / 32);             // (16, 16) = 256 blocks
    pair_kernel<<<pgrid, 256>>>(W2, b2, out);
}